// round 5
// baseline (speedup 1.0000x reference)
#include <cuda_runtime.h>
#include <cstdint>

// GraphSAGE fused layer kernel for GB300 (sm_103a).
// Layer: A = [h | mean_k h[idx_k]]  (N x 256),  Z = A @ W + b,  h' = relu(Z).
// Inputs (metadata order): feats f32[100000*128], neigh_idx i32[2*100000*16],
//                          Ws f32[2*256*128], bs f32[2*128]. Output f32[100000*128].

#define N_NODES 100000
#define D 128
#define KNE 16
#define BM 64
#define NTHREADS 256

// Inter-layer activation scratch (51.2 MB). __device__ global: allocation-free.
__device__ float g_h[(size_t)N_NODES * D];

__device__ __forceinline__ unsigned long long pack2(float x) {
    unsigned long long r;
    asm("mov.b64 %0, {%1, %1};" : "=l"(r) : "f"(x));
    return r;
}

__device__ __forceinline__ void ffma2(unsigned long long& d,
                                      unsigned long long a,
                                      unsigned long long b) {
    // packed 2x fp32 fma: d.lo += a.lo*b.lo ; d.hi += a.hi*b.hi
    asm("fma.rn.f32x2 %0, %1, %2, %0;" : "+l"(d) : "l"(a), "l"(b));
}

__device__ __forceinline__ void unpack2(unsigned long long v, float& lo, float& hi) {
    asm("mov.b64 {%0, %1}, %2;" : "=f"(lo), "=f"(hi) : "l"(v));
}

template <bool RELU>
__global__ void __launch_bounds__(NTHREADS, 1)
sage_layer(const float* __restrict__ h_in,
           const int*   __restrict__ nidx,
           const float* __restrict__ W,     // [256][128] row-major
           const float* __restrict__ bias,  // [128]
           float*       __restrict__ out)   // [N][128]
{
    extern __shared__ float smem[];
    float* W_s = smem;                // [256][128]  128 KB
    float* A_s = smem + 256 * 128;    // [64][256]    64 KB

    const int tid    = threadIdx.x;
    const int base   = blockIdx.x * BM;
    const int nvalid = min(BM, N_NODES - base);

    // ---- load W into smem (coalesced float4) ----
    {
        const float4* Wg  = (const float4*)W;
        float4*       Ws4 = (float4*)W_s;
        #pragma unroll
        for (int i = tid; i < (256 * 128) / 4; i += NTHREADS)
            Ws4[i] = Wg[i];
    }

    // ---- self features -> A_s[node][0:128] ----
    for (int i = tid; i < BM * (D / 4); i += NTHREADS) {
        int node = i >> 5;          // D/4 = 32 float4 per row
        int c4   = i & 31;
        if (node < nvalid) {
            float4 v = ((const float4*)(h_in + (size_t)(base + node) * D))[c4];
            ((float4*)(A_s + node * 256))[c4] = v;
        }
    }

    // ---- neighbor mean -> A_s[node][128:256] (one warp per 8 nodes) ----
    {
        const int warp = tid >> 5;
        const int lane = tid & 31;
        #pragma unroll
        for (int nl = 0; nl < 8; nl++) {
            int node = warp * 8 + nl;
            if (node < nvalid) {
                const int* nrow = nidx + (size_t)(base + node) * KNE;
                int myidx = (lane < KNE) ? nrow[lane] : 0;
                float4 acc = make_float4(0.f, 0.f, 0.f, 0.f);
                #pragma unroll
                for (int j = 0; j < KNE; j++) {
                    int nb = __shfl_sync(0xffffffffu, myidx, j);
                    float4 v = ((const float4*)(h_in + (size_t)nb * D))[lane];
                    acc.x += v.x; acc.y += v.y; acc.z += v.z; acc.w += v.w;
                }
                const float s = 1.0f / 16.0f;
                acc.x *= s; acc.y *= s; acc.z *= s; acc.w *= s;
                ((float4*)(A_s + node * 256 + 128))[lane] = acc;
            }
        }
    }
    __syncthreads();

    // ---- GEMM: each thread computes 4 rows x 8 cols (as 4 packed pairs) ----
    const int tx = tid & 15;   // cols tx*8 .. tx*8+7
    const int ty = tid >> 4;   // rows ty*4 .. ty*4+3

    unsigned long long acc[4][4];
    #pragma unroll
    for (int i = 0; i < 4; i++)
        #pragma unroll
        for (int j = 0; j < 4; j++)
            acc[i][j] = 0ULL;   // packed (0.0f, 0.0f)

    const float* A0 = A_s + (ty * 4 + 0) * 256;
    const float* A1 = A0 + 256;
    const float* A2 = A1 + 256;
    const float* A3 = A2 + 256;

    #pragma unroll 8
    for (int k = 0; k < 256; k++) {
        const ulonglong2* Bp = (const ulonglong2*)(W_s + k * 128 + tx * 8);
        ulonglong2 b01 = Bp[0];   // packed cols (0,1) and (2,3)
        ulonglong2 b23 = Bp[1];   // packed cols (4,5) and (6,7)
        unsigned long long a0 = pack2(A0[k]);
        unsigned long long a1 = pack2(A1[k]);
        unsigned long long a2 = pack2(A2[k]);
        unsigned long long a3 = pack2(A3[k]);
        ffma2(acc[0][0], a0, b01.x); ffma2(acc[0][1], a0, b01.y);
        ffma2(acc[0][2], a0, b23.x); ffma2(acc[0][3], a0, b23.y);
        ffma2(acc[1][0], a1, b01.x); ffma2(acc[1][1], a1, b01.y);
        ffma2(acc[1][2], a1, b23.x); ffma2(acc[1][3], a1, b23.y);
        ffma2(acc[2][0], a2, b01.x); ffma2(acc[2][1], a2, b01.y);
        ffma2(acc[2][2], a2, b23.x); ffma2(acc[2][3], a2, b23.y);
        ffma2(acc[3][0], a3, b01.x); ffma2(acc[3][1], a3, b01.y);
        ffma2(acc[3][2], a3, b23.x); ffma2(acc[3][3], a3, b23.y);
    }

    // ---- epilogue: + bias, optional relu, store ----
    float2 bb[4];
    #pragma unroll
    for (int j = 0; j < 4; j++)
        bb[j] = ((const float2*)(bias + tx * 8))[j];

    #pragma unroll
    for (int i = 0; i < 4; i++) {
        int node = ty * 4 + i;
        if (node < nvalid) {
            float* orow = out + (size_t)(base + node) * D + tx * 8;
            #pragma unroll
            for (int j = 0; j < 4; j++) {
                float lo, hi;
                unpack2(acc[i][j], lo, hi);
                lo += bb[j].x;
                hi += bb[j].y;
                if (RELU) { lo = fmaxf(lo, 0.f); hi = fmaxf(hi, 0.f); }
                ((float2*)orow)[j] = make_float2(lo, hi);
            }
        }
    }
}

extern "C" void kernel_launch(void* const* d_in, const int* in_sizes, int n_in,
                              void* d_out, int out_size) {
    const float* feats = (const float*)d_in[0];
    const int*   nidx  = (const int*)d_in[1];
    const float* Ws    = (const float*)d_in[2];
    const float* bs    = (const float*)d_in[3];
    float*       out   = (float*)d_out;

    void* hbuf = nullptr;
    cudaGetSymbolAddress(&hbuf, g_h);
    float* h1 = (float*)hbuf;

    const size_t SMEM = (size_t)(256 * 128 + BM * 256) * sizeof(float); // 192 KB
    cudaFuncSetAttribute(sage_layer<true>,  cudaFuncAttributeMaxDynamicSharedMemorySize, (int)SMEM);
    cudaFuncSetAttribute(sage_layer<false>, cudaFuncAttributeMaxDynamicSharedMemorySize, (int)SMEM);

    const int grid = (N_NODES + BM - 1) / BM;  // 1563

    // layer 0: feats -> g_h = relu(cat @ W0 + b0)
    sage_layer<true><<<grid, NTHREADS, SMEM>>>(
        feats, nidx, Ws, bs, h1);
    // layer 1: g_h -> out = cat @ W1 + b1  (pre-relu)
    sage_layer<false><<<grid, NTHREADS, SMEM>>>(
        h1, nidx + (size_t)N_NODES * KNE, Ws + 256 * 128, bs + 128, out);
}

// round 6
// speedup vs baseline: 1.2595x; 1.2595x over previous
#include <cuda_runtime.h>
#include <cstdint>

// GraphSAGE fused layer kernel for GB300 (sm_103a).  R5: k-pair-interleaved W
// in smem (natural f32x2 operands, no pack MOVs), conflict-free scattered-column
// register blocking (4 rows x 8 cols / thread), 2-node-concurrent gather (MLP 32),
// two-phase k loop so A_s holds one 64x128 tile.
//
// Layer: Z = [h | mean_k h[idx_k]] @ W + b ; h' = relu(Z).
// Inputs: feats f32[100000*128], neigh_idx i32[2*100000*16],
//         Ws f32[2*256*128], bs f32[2*128].  Output f32[100000*128].

#define N_NODES 100000
#define D 128
#define KNE 16
#define BM 64
#define NTHREADS 256
#define SA 132              // A_s row stride in floats (pad 4: bank-skew + 16B align)

typedef unsigned long long ull;

// Inter-layer activation scratch (51.2 MB). __device__ global: allocation-free.
__device__ float g_h[(size_t)N_NODES * D];

__device__ __forceinline__ void ffma2(ull& d, ull a, ull b) {
    asm("fma.rn.f32x2 %0, %1, %2, %0;" : "+l"(d) : "l"(a), "l"(b));
}
__device__ __forceinline__ ull add2(ull a, ull b) {
    ull r; asm("add.rn.f32x2 %0, %1, %2;" : "=l"(r) : "l"(a), "l"(b)); return r;
}
__device__ __forceinline__ ull mul2(ull a, ull b) {
    ull r; asm("mul.rn.f32x2 %0, %1, %2;" : "=l"(r) : "l"(a), "l"(b)); return r;
}
__device__ __forceinline__ ull pack2(float x) {
    ull r; asm("mov.b64 %0, {%1, %1};" : "=l"(r) : "f"(x)); return r;
}
__device__ __forceinline__ void unpack2(ull v, float& lo, float& hi) {
    asm("mov.b64 {%0, %1}, %2;" : "=f"(lo), "=f"(hi) : "l"(v));
}

template <bool RELU>
__global__ void __launch_bounds__(NTHREADS, 1)
sage_layer(const float* __restrict__ h_in,
           const int*   __restrict__ nidx,
           const float* __restrict__ W,     // [256][128] row-major
           const float* __restrict__ bias,  // [128]
           float*       __restrict__ out)   // [N][128]
{
    extern __shared__ float smem[];
    float* Wi_s = smem;                 // interleaved [128 k2][128 c][2] = 128 KB
    float* A_s  = smem + 256 * 128;     // [64][SA] = 33 KB (one k-phase tile)

    const int tid  = threadIdx.x;
    const int base = blockIdx.x * BM;
    const int warp = tid >> 5;
    const int lane = tid & 31;

    // ---- W -> smem, interleaved by k-pairs: Wi[k2*256 + c*2 + p] = W[2k2+p][c]
    for (int i = tid; i < 128 * 32; i += NTHREADS) {
        int k2 = i >> 5, c4 = i & 31;
        float4 w0 = ((const float4*)(W + (size_t)(2 * k2)     * 128))[c4];
        float4 w1 = ((const float4*)(W + (size_t)(2 * k2 + 1) * 128))[c4];
        float* dst = Wi_s + k2 * 256 + c4 * 8;
        ((float4*)dst)[0] = make_float4(w0.x, w1.x, w0.y, w1.y);
        ((float4*)dst)[1] = make_float4(w0.z, w1.z, w0.w, w1.w);
    }

    // ---- self features -> A_s (phase-1 tile) ----
    for (int i = tid; i < BM * 32; i += NTHREADS) {
        int node = i >> 5, c4 = i & 31;
        if (base + node < N_NODES) {
            float4 v = ((const float4*)(h_in + (size_t)(base + node) * D))[c4];
            ((float4*)(A_s + node * SA))[c4] = v;
        }
    }
    __syncthreads();

    // ---- GEMM setup: thread owns rows {ty+16i}, cols {tx+16m} ----
    const int tx = tid & 15;
    const int ty = tid >> 4;

    ull acc[4][8];
    #pragma unroll
    for (int i = 0; i < 4; i++)
        #pragma unroll
        for (int m = 0; m < 8; m++) acc[i][m] = 0ULL;

    // ---- phase 1: k = 0..127 (self) ----
    {
        const float* Wp = Wi_s;                     // k2 0..63
        #pragma unroll 4
        for (int k2 = 0; k2 < 64; k2++) {
            const float* wrow = Wp + k2 * 256;
            ull b[8];
            #pragma unroll
            for (int m = 0; m < 8; m++)
                b[m] = *(const ull*)(wrow + (tx + 16 * m) * 2);
            ull a[4];
            #pragma unroll
            for (int i = 0; i < 4; i++)
                a[i] = *(const ull*)(A_s + (ty + 16 * i) * SA + k2 * 2);
            #pragma unroll
            for (int i = 0; i < 4; i++)
                #pragma unroll
                for (int m = 0; m < 8; m++)
                    ffma2(acc[i][m], a[i], b[m]);
        }
    }
    __syncthreads();

    // ---- neighbor means -> A_s (phase-2 tile); 2 nodes per warp concurrently ----
    {
        const ull s16 = pack2(1.0f / 16.0f);
        #pragma unroll
        for (int pp = 0; pp < 4; pp++) {
            int n0 = warp * 8 + pp * 2;
            int n1 = n0 + 1;
            bool v0 = (base + n0) < N_NODES;
            bool v1 = (base + n1) < N_NODES;
            int my = 0;
            if (lane < 16) { if (v0) my = nidx[(size_t)(base + n0) * KNE + lane]; }
            else           { if (v1) my = nidx[(size_t)(base + n1) * KNE + (lane - 16)]; }
            ull a0x = 0, a0y = 0, a1x = 0, a1y = 0;
            #pragma unroll
            for (int j = 0; j < 16; j++) {
                int i0 = __shfl_sync(0xffffffffu, my, j);
                int i1 = __shfl_sync(0xffffffffu, my, j + 16);
                float4 q0 = ((const float4*)(h_in + (size_t)i0 * D))[lane];
                float4 q1 = ((const float4*)(h_in + (size_t)i1 * D))[lane];
                ulonglong2 p0 = *(ulonglong2*)&q0;
                ulonglong2 p1 = *(ulonglong2*)&q1;
                a0x = add2(a0x, p0.x); a0y = add2(a0y, p0.y);
                a1x = add2(a1x, p1.x); a1y = add2(a1y, p1.y);
            }
            if (v0) {
                ulonglong2 r; r.x = mul2(a0x, s16); r.y = mul2(a0y, s16);
                *(ulonglong2*)(A_s + n0 * SA + lane * 4) = r;
            }
            if (v1) {
                ulonglong2 r; r.x = mul2(a1x, s16); r.y = mul2(a1y, s16);
                *(ulonglong2*)(A_s + n1 * SA + lane * 4) = r;
            }
        }
    }
    __syncthreads();

    // ---- phase 2: k = 128..255 (agg), W rows 128.. ----
    {
        const float* Wp = Wi_s + 64 * 256;          // k2 64..127
        #pragma unroll 4
        for (int k2 = 0; k2 < 64; k2++) {
            const float* wrow = Wp + k2 * 256;
            ull b[8];
            #pragma unroll
            for (int m = 0; m < 8; m++)
                b[m] = *(const ull*)(wrow + (tx + 16 * m) * 2);
            ull a[4];
            #pragma unroll
            for (int i = 0; i < 4; i++)
                a[i] = *(const ull*)(A_s + (ty + 16 * i) * SA + k2 * 2);
            #pragma unroll
            for (int i = 0; i < 4; i++)
                #pragma unroll
                for (int m = 0; m < 8; m++)
                    ffma2(acc[i][m], a[i], b[m]);
        }
    }

    // ---- epilogue: combine even/odd-k halves, +bias, relu, store ----
    float bv[8];
    #pragma unroll
    for (int m = 0; m < 8; m++) bv[m] = bias[m * 16 + tx];

    #pragma unroll
    for (int i = 0; i < 4; i++) {
        int r = ty + 16 * i;
        if (base + r < N_NODES) {
            float* orow = out + (size_t)(base + r) * D;
            #pragma unroll
            for (int m = 0; m < 8; m++) {
                float lo, hi;
                unpack2(acc[i][m], lo, hi);
                float v = lo + hi + bv[m];
                if (RELU) v = fmaxf(v, 0.0f);
                orow[m * 16 + tx] = v;
            }
        }
    }
}

extern "C" void kernel_launch(void* const* d_in, const int* in_sizes, int n_in,
                              void* d_out, int out_size) {
    const float* feats = (const float*)d_in[0];
    const int*   nidx  = (const int*)d_in[1];
    const float* Ws    = (const float*)d_in[2];
    const float* bs    = (const float*)d_in[3];
    float*       out   = (float*)d_out;

    void* hbuf = nullptr;
    cudaGetSymbolAddress(&hbuf, g_h);
    float* h1 = (float*)hbuf;

    const size_t SMEM = (size_t)(256 * 128 + BM * SA) * sizeof(float); // 164864 B
    cudaFuncSetAttribute(sage_layer<true>,  cudaFuncAttributeMaxDynamicSharedMemorySize, (int)SMEM);
    cudaFuncSetAttribute(sage_layer<false>, cudaFuncAttributeMaxDynamicSharedMemorySize, (int)SMEM);

    const int grid = (N_NODES + BM - 1) / BM;  // 1563

    // layer 0: feats -> g_h = relu(cat @ W0 + b0)
    sage_layer<true><<<grid, NTHREADS, SMEM>>>(feats, nidx, Ws, bs, h1);
    // layer 1: g_h -> out = cat @ W1 + b1  (pre-relu)
    sage_layer<false><<<grid, NTHREADS, SMEM>>>(
        h1, nidx + (size_t)N_NODES * KNE, Ws + 256 * 128, bs + 128, out);
}

// round 7
// speedup vs baseline: 1.6189x; 1.2853x over previous
#include <cuda_runtime.h>
#include <cstdint>

// GraphSAGE fused layer kernel for GB300 (sm_103a).  R6: persistent CTAs
// (W loaded once per SM), gather software-pipelined INTO the phase-1 GEMM
// k-loop (4-deep LDG ring, ~512 cyc prefetch distance > L2 latency),
// separate A_self/A_agg smem tiles, indices staged in smem (broadcast LDS).
//
// Layer: Z = [h | mean_k h[idx_k]] @ W + b ; h' = relu(Z).

#define N_NODES 100000
#define D 128
#define KNE 16
#define BM 64
#define NTHREADS 256
#define SA 132                      // A row stride in floats (bank skew, 16B-mult)
#define TILES ((N_NODES + BM - 1) / BM)   // 1563
#define GRID 152

typedef unsigned long long ull;

// Inter-layer activation scratch (51.2 MB). __device__ global: allocation-free.
__device__ float g_h[(size_t)N_NODES * D];

__device__ __forceinline__ void ffma2(ull& d, ull a, ull b) {
    asm("fma.rn.f32x2 %0, %1, %2, %0;" : "+l"(d) : "l"(a), "l"(b));
}
__device__ __forceinline__ ull add2(ull a, ull b) {
    ull r; asm("add.rn.f32x2 %0, %1, %2;" : "=l"(r) : "l"(a), "l"(b)); return r;
}
__device__ __forceinline__ ull mul2(ull a, ull b) {
    ull r; asm("mul.rn.f32x2 %0, %1, %2;" : "=l"(r) : "l"(a), "l"(b)); return r;
}
__device__ __forceinline__ ull pack2(float x) {
    ull r; asm("mov.b64 %0, {%1, %1};" : "=l"(r) : "f"(x)); return r;
}
__device__ __forceinline__ void unpack2(ull v, float& lo, float& hi) {
    asm("mov.b64 {%0, %1}, %2;" : "=f"(lo), "=f"(hi) : "l"(v));
}

template <bool RELU>
__global__ void __launch_bounds__(NTHREADS, 1)
sage_layer(const float* __restrict__ h_in,
           const int*   __restrict__ nidx,
           const float* __restrict__ W,     // [256][128] row-major
           const float* __restrict__ bias,  // [128]
           float*       __restrict__ out)   // [N][128]
{
    extern __shared__ float smem[];
    float* Wi_s   = smem;                   // interleaved [128 k2][128 c][2] = 128 KB
    float* A_self = smem + 256 * 128;       // [64][SA]  33 KB
    float* A_agg  = A_self + BM * SA;       // [64][SA]  33 KB
    int*   idx_s  = (int*)(A_agg + BM * SA);// [64][16]   4 KB

    const int tid  = threadIdx.x;
    const int warp = tid >> 5;
    const int lane = tid & 31;
    const int tx   = tid & 15;
    const int ty   = tid >> 4;

    // ---- W -> smem once, interleaved by k-pairs: Wi[k2*256 + c*2 + p] = W[2k2+p][c]
    for (int i = tid; i < 128 * 32; i += NTHREADS) {
        int k2 = i >> 5, c4 = i & 31;
        float4 w0 = ((const float4*)(W + (size_t)(2 * k2)     * 128))[c4];
        float4 w1 = ((const float4*)(W + (size_t)(2 * k2 + 1) * 128))[c4];
        float* dst = Wi_s + k2 * 256 + c4 * 8;
        ((float4*)dst)[0] = make_float4(w0.x, w1.x, w0.y, w1.y);
        ((float4*)dst)[1] = make_float4(w0.z, w1.z, w0.w, w1.w);
    }

    float bv[8];
    #pragma unroll
    for (int m = 0; m < 8; m++) bv[m] = bias[m * 16 + tx];

    const ull s16 = pack2(1.0f / 16.0f);

    for (int tile = blockIdx.x; tile < TILES; tile += gridDim.x) {
        const int base = tile * BM;

        __syncthreads();   // protect A_self/A_agg/idx_s vs previous tile readers

        // ---- self features -> A_self ----
        #pragma unroll
        for (int i = tid; i < BM * 32; i += NTHREADS) {
            int node = i >> 5, c4 = i & 31;
            if (base + node < N_NODES)
                ((float4*)(A_self + node * SA))[c4] =
                    ((const float4*)(h_in + (size_t)(base + node) * D))[c4];
        }
        // ---- neighbor indices -> idx_s (zero-fill invalid) ----
        {
            int node = tid >> 2;
            int4 v = make_int4(0, 0, 0, 0);
            if (base + node < N_NODES)
                v = ((const int4*)(nidx + (size_t)base * KNE))[tid];
            ((int4*)idx_s)[tid] = v;
        }
        __syncthreads();

        ull acc[4][8];
        #pragma unroll
        for (int i = 0; i < 4; i++)
            #pragma unroll
            for (int m = 0; m < 8; m++) acc[i][m] = 0ULL;

        // ---- gather pipeline state: warp owns nodes warp*8..warp*8+7 (4 pairs x 16 steps)
        ull g0x = 0, g0y = 0, g1x = 0, g1y = 0;
        float4 bufA[4], bufB[4];

        // prologue: issue gather loads for steps 0..3 (pair 0)
        #pragma unroll
        for (int j = 0; j < 4; j++) {
            int n0 = warp * 8;
            int i0 = idx_s[n0 * 16 + j];
            int i1 = idx_s[n0 * 16 + 16 + j];
            bufA[j] = ((const float4*)(h_in + (size_t)i0 * D))[lane];
            bufB[j] = ((const float4*)(h_in + (size_t)i1 * D))[lane];
        }

        // ---- phase 1: GEMM over self half (k=0..127) + interleaved gather ----
        #pragma unroll 4
        for (int k2 = 0; k2 < 64; k2++) {
            // consume gather step j = k2 (loaded 4 iterations ago)
            {
                ulonglong2 pA = *(ulonglong2*)&bufA[k2 & 3];
                ulonglong2 pB = *(ulonglong2*)&bufB[k2 & 3];
                g0x = add2(g0x, pA.x); g0y = add2(g0y, pA.y);
                g1x = add2(g1x, pB.x); g1y = add2(g1y, pB.y);
            }
            // issue gather step j = k2 + 4
            if (k2 < 60) {
                int j  = k2 + 4;
                int n0 = warp * 8 + (j >> 4) * 2;
                int s  = j & 15;
                int i0 = idx_s[n0 * 16 + s];
                int i1 = idx_s[n0 * 16 + 16 + s];
                bufA[k2 & 3] = ((const float4*)(h_in + (size_t)i0 * D))[lane];
                bufB[k2 & 3] = ((const float4*)(h_in + (size_t)i1 * D))[lane];
            }
            // pair boundary: write mean to A_agg, reset accumulators
            if ((k2 & 15) == 15) {
                int n0 = warp * 8 + (k2 >> 4) * 2;
                if (base + n0 < N_NODES) {
                    ulonglong2 r; r.x = mul2(g0x, s16); r.y = mul2(g0y, s16);
                    *(ulonglong2*)(A_agg + n0 * SA + lane * 4) = r;
                }
                if (base + n0 + 1 < N_NODES) {
                    ulonglong2 r; r.x = mul2(g1x, s16); r.y = mul2(g1y, s16);
                    *(ulonglong2*)(A_agg + (n0 + 1) * SA + lane * 4) = r;
                }
                g0x = 0; g0y = 0; g1x = 0; g1y = 0;
            }
            // GEMM body (self half)
            const float* wrow = Wi_s + k2 * 256;
            ull b[8];
            #pragma unroll
            for (int m = 0; m < 8; m++)
                b[m] = *(const ull*)(wrow + (tx + 16 * m) * 2);
            ull a[4];
            #pragma unroll
            for (int i = 0; i < 4; i++)
                a[i] = *(const ull*)(A_self + (ty + 16 * i) * SA + k2 * 2);
            #pragma unroll
            for (int i = 0; i < 4; i++)
                #pragma unroll
                for (int m = 0; m < 8; m++)
                    ffma2(acc[i][m], a[i], b[m]);
        }
        __syncthreads();   // A_agg complete

        // ---- phase 2: GEMM over agg half (k=128..255) ----
        #pragma unroll 4
        for (int k2 = 0; k2 < 64; k2++) {
            const float* wrow = Wi_s + (64 + k2) * 256;
            ull b[8];
            #pragma unroll
            for (int m = 0; m < 8; m++)
                b[m] = *(const ull*)(wrow + (tx + 16 * m) * 2);
            ull a[4];
            #pragma unroll
            for (int i = 0; i < 4; i++)
                a[i] = *(const ull*)(A_agg + (ty + 16 * i) * SA + k2 * 2);
            #pragma unroll
            for (int i = 0; i < 4; i++)
                #pragma unroll
                for (int m = 0; m < 8; m++)
                    ffma2(acc[i][m], a[i], b[m]);
        }

        // ---- epilogue: combine even/odd-k halves, +bias, relu, store ----
        #pragma unroll
        for (int i = 0; i < 4; i++) {
            int r = ty + 16 * i;
            if (base + r < N_NODES) {
                float* orow = out + (size_t)(base + r) * D;
                #pragma unroll
                for (int m = 0; m < 8; m++) {
                    float lo, hi;
                    unpack2(acc[i][m], lo, hi);
                    float v = lo + hi + bv[m];
                    if (RELU) v = fmaxf(v, 0.0f);
                    orow[m * 16 + tx] = v;
                }
            }
        }
    }
}

extern "C" void kernel_launch(void* const* d_in, const int* in_sizes, int n_in,
                              void* d_out, int out_size) {
    const float* feats = (const float*)d_in[0];
    const int*   nidx  = (const int*)d_in[1];
    const float* Ws    = (const float*)d_in[2];
    const float* bs    = (const float*)d_in[3];
    float*       out   = (float*)d_out;

    void* hbuf = nullptr;
    cudaGetSymbolAddress(&hbuf, g_h);
    float* h1 = (float*)hbuf;

    const size_t SMEM = (size_t)(256 * 128 + 2 * BM * SA) * sizeof(float)
                      + (size_t)BM * KNE * sizeof(int);   // 202752 B
    cudaFuncSetAttribute(sage_layer<true>,  cudaFuncAttributeMaxDynamicSharedMemorySize, (int)SMEM);
    cudaFuncSetAttribute(sage_layer<false>, cudaFuncAttributeMaxDynamicSharedMemorySize, (int)SMEM);

    // layer 0: feats -> g_h = relu(cat @ W0 + b0)
    sage_layer<true><<<GRID, NTHREADS, SMEM>>>(feats, nidx, Ws, bs, h1);
    // layer 1: g_h -> out = cat @ W1 + b1  (pre-relu)
    sage_layer<false><<<GRID, NTHREADS, SMEM>>>(
        h1, nidx + (size_t)N_NODES * KNE, Ws + 256 * 128, bs + 128, out);
}